// round 4
// baseline (speedup 1.0000x reference)
#include <cuda_runtime.h>
#include <cstdint>

#define CH_IN 32
#define CH_Y  16
#define IMG_H 256
#define IMG_W 256
#define NB    16
#define CHS   (IMG_H * IMG_W)   // channel stride (elements)
#define CHS2  (CHS / 2)         // in float2
#define NT    128               // threads/block; one (b,h) row, 2 px/thread

union F2U { float2 f; uint64_t u; };

// Packed dual-fp32 FMA: d.{x,y} += w.{x,y} * x.{x,y}  (sm_103a FFMA2)
__device__ __forceinline__ void fma2(uint64_t& d, uint64_t w, uint64_t x) {
    asm("fma.rn.f32x2 %0, %1, %2, %0;" : "+l"(d) : "l"(w), "l"(x));
}
__device__ __forceinline__ uint64_t bcast2(float s) {
    F2U t; t.f.x = s; t.f.y = s; return t.u;
}

// Single fused pass: q,k,v projections together (v is softmax-independent),
// inputs straight from global (coalesced LDG.64), concat(c) written through
// from the same registers. No row staging, no second p traversal.
__global__ void __launch_bounds__(NT, 4) cross_attn_kernel(
    const float* __restrict__ cin, const float* __restrict__ pin,
    const float* __restrict__ Wq,  const float* __restrict__ bq,
    const float* __restrict__ Wk,  const float* __restrict__ bk,
    const float* __restrict__ Wv,  const float* __restrict__ bv,
    const float* __restrict__ Wy,  const float* __restrict__ by,
    float* __restrict__ out)
{
    // Projection weights as duplicated pairs: one LDS.128 = 2 packed operands.
    __shared__ float2 wq_d[CH_Y * CH_IN];       // 4KB each
    __shared__ float2 wk_d[CH_Y * CH_IN];
    __shared__ float2 wv_d[CH_Y * CH_IN];
    __shared__ float4 wy_s[CH_IN * CH_Y / 4];   // scalar, for output conv
    __shared__ float  bq_s[CH_Y], bk_s[CH_Y], bv_s[CH_Y], by_s[CH_IN];
    __shared__ float  red[4][CH_Y];

    const int tid = threadIdx.x;

    {   // weight setup: each thread expands 4 scalars/matrix into dup pairs
        float4 a = ((const float4*)Wq)[tid];
        wq_d[tid*4+0] = make_float2(a.x, a.x); wq_d[tid*4+1] = make_float2(a.y, a.y);
        wq_d[tid*4+2] = make_float2(a.z, a.z); wq_d[tid*4+3] = make_float2(a.w, a.w);
        float4 bm = ((const float4*)Wk)[tid];
        wk_d[tid*4+0] = make_float2(bm.x, bm.x); wk_d[tid*4+1] = make_float2(bm.y, bm.y);
        wk_d[tid*4+2] = make_float2(bm.z, bm.z); wk_d[tid*4+3] = make_float2(bm.w, bm.w);
        float4 cm = ((const float4*)Wv)[tid];
        wv_d[tid*4+0] = make_float2(cm.x, cm.x); wv_d[tid*4+1] = make_float2(cm.y, cm.y);
        wv_d[tid*4+2] = make_float2(cm.z, cm.z); wv_d[tid*4+3] = make_float2(cm.w, cm.w);
        wy_s[tid] = ((const float4*)Wy)[tid];
    }
    if (tid < CH_Y)  { bq_s[tid] = bq[tid]; bk_s[tid] = bk[tid]; bv_s[tid] = bv[tid]; }
    if (tid < CH_IN) { by_s[tid] = by[tid]; }
    __syncthreads();

    const int h = blockIdx.x & (IMG_H - 1);
    const int b = blockIdx.x >> 8;

    const size_t base = (size_t)b * CH_IN * CHS + (size_t)h * IMG_W;
    const float2* cg2 = (const float2*)(cin + base);   // + ch*CHS2 + tid
    const float2* pg2 = (const float2*)(pin + base);
    float2* oy2 = (float2*)(out + (size_t)b * 2 * CH_IN * CHS + (size_t)h * IMG_W);
    float2* oc2 = oy2 + (size_t)CH_IN * CHS2;          // concat(c) half

    uint64_t q[CH_Y], k[CH_Y], v[CH_Y];
#pragma unroll
    for (int o = 0; o < CH_Y; o++) {
        q[o] = bcast2(bq_s[o]); k[o] = bcast2(bk_s[o]); v[o] = bcast2(bv_s[o]);
    }

    // -------- fused q/k/v projection over 32 channels, 4 per step --------
#pragma unroll
    for (int c4 = 0; c4 < CH_IN / 4; c4++) {
        F2U cv[4], pv[4];
#pragma unroll
        for (int j = 0; j < 4; j++) {
            int ch = c4 * 4 + j;
            cv[j].f = cg2[(size_t)ch * CHS2 + tid];
            pv[j].f = pg2[(size_t)ch * CHS2 + tid];
        }
#pragma unroll
        for (int j = 0; j < 4; j++)
            oc2[(size_t)(c4 * 4 + j) * CHS2 + tid] = cv[j].f;   // concat write-through

#pragma unroll
        for (int o = 0; o < CH_Y; o++) {
            const int wbase = o * CH_IN + c4 * 4;
            ulonglong2 wa = *(const ulonglong2*)&wq_d[wbase];       // pairs 0,1
            ulonglong2 wb = *(const ulonglong2*)&wq_d[wbase + 2];   // pairs 2,3
            fma2(q[o], wa.x, cv[0].u); fma2(q[o], wa.y, cv[1].u);
            fma2(q[o], wb.x, cv[2].u); fma2(q[o], wb.y, cv[3].u);
            ulonglong2 ka = *(const ulonglong2*)&wk_d[wbase];
            ulonglong2 kb = *(const ulonglong2*)&wk_d[wbase + 2];
            fma2(k[o], ka.x, pv[0].u); fma2(k[o], ka.y, pv[1].u);
            fma2(k[o], kb.x, pv[2].u); fma2(k[o], kb.y, pv[3].u);
            ulonglong2 va = *(const ulonglong2*)&wv_d[wbase];
            ulonglong2 vb = *(const ulonglong2*)&wv_d[wbase + 2];
            fma2(v[o], va.x, pv[0].u); fma2(v[o], va.y, pv[1].u);
            fma2(v[o], vb.x, pv[2].u); fma2(v[o], vb.y, pv[3].u);
        }
    }

    // -------- exp(q*k); softmax over width via block reduction --------
    // No max-subtraction: |q*k| is O(1..10); fp32 exp is safe, result
    // identical after normalization.
    float2 e[CH_Y];
#pragma unroll
    for (int o = 0; o < CH_Y; o++) {
        F2U qq, kk; qq.u = q[o]; kk.u = k[o];
        e[o].x = __expf(qq.f.x * kk.f.x);
        e[o].y = __expf(qq.f.y * kk.f.y);
    }

    const int lane = tid & 31;
    const int wrp  = tid >> 5;
#pragma unroll
    for (int o = 0; o < CH_Y; o++) {
        float s = e[o].x + e[o].y;
#pragma unroll
        for (int d = 16; d > 0; d >>= 1) s += __shfl_xor_sync(0xffffffffu, s, d);
        if (lane == 0) red[wrp][o] = s;
    }
    __syncthreads();

    // y = softmax * v   (e overwritten with final y values)
#pragma unroll
    for (int o = 0; o < CH_Y; o++) {
        float inv = __frcp_rn(red[0][o] + red[1][o] + red[2][o] + red[3][o]);
        F2U vv; vv.u = v[o];
        e[o].x *= inv * vv.f.x;
        e[o].y *= inv * vv.f.y;
    }

    // -------- output conv1x1 --------
#pragma unroll
    for (int ic = 0; ic < CH_IN; ic++) {
        float2 acc; acc.x = acc.y = by_s[ic];
#pragma unroll
        for (int o4 = 0; o4 < CH_Y / 4; o4++) {
            float4 w4 = wy_s[ic * (CH_Y / 4) + o4];
            acc.x += w4.x * e[o4*4+0].x + w4.y * e[o4*4+1].x
                   + w4.z * e[o4*4+2].x + w4.w * e[o4*4+3].x;
            acc.y += w4.x * e[o4*4+0].y + w4.y * e[o4*4+1].y
                   + w4.z * e[o4*4+2].y + w4.w * e[o4*4+3].y;
        }
        oy2[(size_t)ic * CHS2 + tid] = acc;
    }
}

extern "C" void kernel_launch(void* const* d_in, const int* in_sizes, int n_in,
                              void* d_out, int out_size)
{
    cross_attn_kernel<<<NB * IMG_H, NT>>>(
        (const float*)d_in[0],  // c
        (const float*)d_in[1],  // p
        (const float*)d_in[2],  // Wq
        (const float*)d_in[3],  // bq
        (const float*)d_in[4],  // Wk
        (const float*)d_in[5],  // bk
        (const float*)d_in[6],  // Wv
        (const float*)d_in[7],  // bv
        (const float*)d_in[8],  // Wy
        (const float*)d_in[9],  // by
        (float*)d_out);
}

// round 5
// speedup vs baseline: 1.6577x; 1.6577x over previous
#include <cuda_runtime.h>
#include <cstdint>

#define CH_IN 32
#define CH_Y  16
#define IMG_H 256
#define IMG_W 256
#define NB    16
#define CHS   (IMG_H * IMG_W)   // channel stride (elements)
#define CHS4  (CHS / 4)
#define CHS2  (CHS / 2)
#define NT    128               // threads/block; one (b,h) row, 2 px/thread

union F2U { float2 f; uint64_t u; };

// sm_103a packed dual-fp32 ops (ptxas never emits these from C++)
__device__ __forceinline__ void fma2(uint64_t& d, uint64_t a, uint64_t b) {
    asm("fma.rn.f32x2 %0, %1, %2, %0;" : "+l"(d) : "l"(a), "l"(b));
}
__device__ __forceinline__ uint64_t mul2(uint64_t a, uint64_t b) {
    uint64_t d; asm("mul.rn.f32x2 %0, %1, %2;" : "=l"(d) : "l"(a), "l"(b)); return d;
}
__device__ __forceinline__ uint64_t bcast2(float s) { F2U t; t.f.x = s; t.f.y = s; return t.u; }

// R3 two-pass structure + f32x2 packing.
// Phase 1: stage p row in smem, concat write-through of c.
// Phase 2a: q,k projection (c from global = L2-resident, p from smem), FFMA2.
// Phase 2b: v projection from smem, FFMA2. Then packed scale + output conv.
__global__ void __launch_bounds__(NT, 4) cross_attn_kernel(
    const float* __restrict__ cin, const float* __restrict__ pin,
    const float* __restrict__ Wq,  const float* __restrict__ bq,
    const float* __restrict__ Wk,  const float* __restrict__ bk,
    const float* __restrict__ Wv,  const float* __restrict__ bv,
    const float* __restrict__ Wy,  const float* __restrict__ by,
    float* __restrict__ out)
{
    extern __shared__ char smraw[];
    float*  sp   = (float*)smraw;                        // 32KB: p row [ch][w]
    float2* wq_d = (float2*)(smraw + 32768);             // dup pairs, 4KB each
    float2* wk_d = wq_d + CH_Y * CH_IN;
    float2* wv_d = wk_d + CH_Y * CH_IN;
    float2* wy_d = wv_d + CH_Y * CH_IN;                  // [ic][o] dup pairs
    float*  bias = (float*)(wy_d + CH_IN * CH_Y);        // bq16|bk16|bv16|by32
    float*  red  = bias + 80;                            // [4][16]

    const int tid = threadIdx.x;

    {   // dup-pair weight expansion: one float4 -> 4 (w,w) pairs per matrix
        float4 a = ((const float4*)Wq)[tid];
        wq_d[tid*4+0] = make_float2(a.x,a.x); wq_d[tid*4+1] = make_float2(a.y,a.y);
        wq_d[tid*4+2] = make_float2(a.z,a.z); wq_d[tid*4+3] = make_float2(a.w,a.w);
        float4 m = ((const float4*)Wk)[tid];
        wk_d[tid*4+0] = make_float2(m.x,m.x); wk_d[tid*4+1] = make_float2(m.y,m.y);
        wk_d[tid*4+2] = make_float2(m.z,m.z); wk_d[tid*4+3] = make_float2(m.w,m.w);
        float4 n = ((const float4*)Wv)[tid];
        wv_d[tid*4+0] = make_float2(n.x,n.x); wv_d[tid*4+1] = make_float2(n.y,n.y);
        wv_d[tid*4+2] = make_float2(n.z,n.z); wv_d[tid*4+3] = make_float2(n.w,n.w);
        float4 y4 = ((const float4*)Wy)[tid];
        wy_d[tid*4+0] = make_float2(y4.x,y4.x); wy_d[tid*4+1] = make_float2(y4.y,y4.y);
        wy_d[tid*4+2] = make_float2(y4.z,y4.z); wy_d[tid*4+3] = make_float2(y4.w,y4.w);
    }
    if (tid < CH_Y)  { bias[tid] = bq[tid]; bias[16+tid] = bk[tid]; bias[32+tid] = bv[tid]; }
    if (tid < CH_IN) { bias[48+tid] = by[tid]; }

    const int h = blockIdx.x & (IMG_H - 1);
    const int b = blockIdx.x >> 8;

    const size_t base = (size_t)b * CH_IN * CHS + (size_t)h * IMG_W;
    const float4* cg = (const float4*)(cin + base);
    const float4* pg = (const float4*)(pin + base);
    float4* ocg = (float4*)(out + (size_t)b * 2 * CH_IN * CHS + (size_t)CH_IN * CHS
                                + (size_t)h * IMG_W);
    float4* sp4 = (float4*)sp;

    // ---------------- Phase 1: stage p + concat copy of c ----------------
#pragma unroll
    for (int half = 0; half < 2; half++) {
        float4 cb[8], pb[8];
#pragma unroll
        for (int i = 0; i < 8; i++) {
            int idx = tid + (half * 8 + i) * NT;            // = ch*64 + w4
            int ch = idx >> 6, w4 = idx & 63;
            cb[i] = cg[(size_t)ch * CHS4 + w4];
            pb[i] = pg[(size_t)ch * CHS4 + w4];
        }
#pragma unroll
        for (int i = 0; i < 8; i++) {
            int idx = tid + (half * 8 + i) * NT;
            int ch = idx >> 6, w4 = idx & 63;
            ocg[(size_t)ch * CHS4 + w4] = cb[i];            // concat(c) half
            sp4[idx] = pb[i];
        }
    }
    __syncthreads();

    // ---------------- Phase 2a: q,k projection (packed) ----------------
    const float2* cp2 = (const float2*)(cin + base);        // + ch*CHS2 + tid
    const float2* sp2 = (const float2*)sp;                  // + ch*128 + tid

    uint64_t q[CH_Y], k[CH_Y];
#pragma unroll
    for (int o = 0; o < CH_Y; o++) { q[o] = bcast2(bias[o]); k[o] = bcast2(bias[16+o]); }

#pragma unroll
    for (int c4 = 0; c4 < CH_IN / 4; c4++) {
        F2U cv[4], pv[4];
#pragma unroll
        for (int j = 0; j < 4; j++) {
            int ch = c4 * 4 + j;
            cv[j].f = cp2[(size_t)ch * CHS2 + tid];         // L2-resident re-read
            pv[j].f = sp2[ch * (IMG_W / 2) + tid];
        }
#pragma unroll
        for (int o = 0; o < CH_Y; o++) {
            const int wb = o * CH_IN + c4 * 4;
            ulonglong2 wa = *(const ulonglong2*)&wq_d[wb];
            ulonglong2 wbq = *(const ulonglong2*)&wq_d[wb + 2];
            fma2(q[o], wa.x, cv[0].u); fma2(q[o], wa.y, cv[1].u);
            fma2(q[o], wbq.x, cv[2].u); fma2(q[o], wbq.y, cv[3].u);
            ulonglong2 ka = *(const ulonglong2*)&wk_d[wb];
            ulonglong2 kb = *(const ulonglong2*)&wk_d[wb + 2];
            fma2(k[o], ka.x, pv[0].u); fma2(k[o], ka.y, pv[1].u);
            fma2(k[o], kb.x, pv[2].u); fma2(k[o], kb.y, pv[3].u);
        }
    }

    // exp(q*k). No max-subtraction: |q*k| O(1..10), fp32 exp safe; result
    // identical after normalization.
    F2U e[CH_Y];
#pragma unroll
    for (int o = 0; o < CH_Y; o++) {
        F2U pr; pr.u = mul2(q[o], k[o]);
        e[o].f.x = __expf(pr.f.x);
        e[o].f.y = __expf(pr.f.y);
    }

    // ---------------- softmax reduction over width ----------------
    const int lane = tid & 31;
    const int wrp  = tid >> 5;
#pragma unroll
    for (int o = 0; o < CH_Y; o++) {
        float s = e[o].f.x + e[o].f.y;
#pragma unroll
        for (int d = 16; d > 0; d >>= 1) s += __shfl_xor_sync(0xffffffffu, s, d);
        if (lane == 0) red[wrp * CH_Y + o] = s;
    }
    __syncthreads();

    // ---------------- Phase 2b: v projection (packed) ----------------
    uint64_t v[CH_Y];
#pragma unroll
    for (int o = 0; o < CH_Y; o++) v[o] = bcast2(bias[32 + o]);

#pragma unroll
    for (int c4 = 0; c4 < CH_IN / 4; c4++) {
        F2U pv[4];
#pragma unroll
        for (int j = 0; j < 4; j++)
            pv[j].f = sp2[(c4 * 4 + j) * (IMG_W / 2) + tid];
#pragma unroll
        for (int o = 0; o < CH_Y; o++) {
            const int wb = o * CH_IN + c4 * 4;
            ulonglong2 va = *(const ulonglong2*)&wv_d[wb];
            ulonglong2 vb = *(const ulonglong2*)&wv_d[wb + 2];
            fma2(v[o], va.x, pv[0].u); fma2(v[o], va.y, pv[1].u);
            fma2(v[o], vb.x, pv[2].u); fma2(v[o], vb.y, pv[3].u);
        }
    }

    // y = softmax(q*k) * v, all packed
#pragma unroll
    for (int o = 0; o < CH_Y; o++) {
        float inv = __frcp_rn(red[o] + red[CH_Y + o] + red[2*CH_Y + o] + red[3*CH_Y + o]);
        e[o].u = mul2(mul2(e[o].u, bcast2(inv)), v[o]);
    }

    // ---------------- output conv1x1 (packed) ----------------
    float2* oy2 = (float2*)(out + (size_t)b * 2 * CH_IN * CHS + (size_t)h * IMG_W);
#pragma unroll
    for (int ic = 0; ic < CH_IN; ic++) {
        uint64_t acc = bcast2(bias[48 + ic]);
#pragma unroll
        for (int o2 = 0; o2 < CH_Y / 2; o2++) {
            ulonglong2 w2 = *(const ulonglong2*)&wy_d[ic * CH_Y + o2 * 2];
            fma2(acc, w2.x, e[o2*2+0].u);
            fma2(acc, w2.y, e[o2*2+1].u);
        }
        F2U r; r.u = acc;
        oy2[(size_t)ic * CHS2 + tid] = r.f;
    }
}

extern "C" void kernel_launch(void* const* d_in, const int* in_sizes, int n_in,
                              void* d_out, int out_size)
{
    const int dyn_smem = 32768                      // p row
                       + 4 * CH_Y * CH_IN * 8       // 4 dup-pair weight mats
                       + 80 * 4 + 64 * 4 + 256;     // bias + red + pad
    cudaFuncSetAttribute(cross_attn_kernel,
                         cudaFuncAttributeMaxDynamicSharedMemorySize, dyn_smem);
    cross_attn_kernel<<<NB * IMG_H, NT, dyn_smem>>>(
        (const float*)d_in[0],  // c
        (const float*)d_in[1],  // p
        (const float*)d_in[2],  // Wq
        (const float*)d_in[3],  // bq
        (const float*)d_in[4],  // Wk
        (const float*)d_in[5],  // bk
        (const float*)d_in[6],  // Wv
        (const float*)d_in[7],  // bv
        (const float*)d_in[8],  // Wy
        (const float*)d_in[9],  // by
        (float*)d_out);
}

// round 6
// speedup vs baseline: 2.4479x; 1.4767x over previous
#include <cuda_runtime.h>
#include <cstdint>

#define CH_IN 32
#define CH_Y  16
#define IMG_H 256
#define IMG_W 256
#define NB    16
#define CHS   (IMG_H * IMG_W)   // channel stride (elements)
#define CHS4  (CHS / 4)
#define CHS2  (CHS / 2)
#define NT    128               // threads/block; one (b,h) row, 2 px/thread

union F2U { float2 f; uint64_t u; };

// sm_103a packed dual-fp32 ops (ptxas never emits these from C++)
__device__ __forceinline__ void fma2(uint64_t& d, uint64_t a, uint64_t b) {
    asm("fma.rn.f32x2 %0, %1, %2, %0;" : "+l"(d) : "l"(a), "l"(b));
}
__device__ __forceinline__ uint64_t mul2(uint64_t a, uint64_t b) {
    uint64_t d; asm("mul.rn.f32x2 %0, %1, %2;" : "=l"(d) : "l"(a), "l"(b)); return d;
}
__device__ __forceinline__ uint64_t add2(uint64_t a, uint64_t b) {
    uint64_t d; asm("add.rn.f32x2 %0, %1, %2;" : "=l"(d) : "l"(a), "l"(b)); return d;
}
__device__ __forceinline__ uint64_t dup2(float x) {
    uint64_t d; asm("mov.b64 %0, {%1, %1};" : "=l"(d) : "f"(x)); return d;
}

// R3 two-pass skeleton + output-channel-packed FFMA2.
// Accumulator q[px][o2] holds channels (2*o2, 2*o2+1) for one pixel; weight
// operand is the NATURAL transposed pair (W[2o2][c], W[2o2+1][c]) -> no
// duplication, same weight-LDS count as R3, half the FMA instructions.
__global__ void __launch_bounds__(NT, 4) cross_attn_kernel(
    const float* __restrict__ cin, const float* __restrict__ pin,
    const float* __restrict__ Wq,  const float* __restrict__ bq,
    const float* __restrict__ Wk,  const float* __restrict__ bk,
    const float* __restrict__ Wv,  const float* __restrict__ bv,
    const float* __restrict__ Wy,  const float* __restrict__ by,
    float* __restrict__ out)
{
    __shared__ float sp[CH_IN * IMG_W];                 // 32KB: p row [ch][w]
    __shared__ __align__(16) float2 wqT[CH_IN * 8];     // [c][o2] o-pairs, 2KB
    __shared__ __align__(16) float2 wkT[CH_IN * 8];
    __shared__ __align__(16) float2 wvT[CH_IN * 8];
    __shared__ __align__(16) float4 wy_s[CH_IN * CH_Y / 4];  // natural o-pairs
    __shared__ float2   bq2[8], bk2[8], bv2[8];
    __shared__ float    by_s[CH_IN];
    __shared__ uint64_t red[4][8];

    const int tid = threadIdx.x;

    // ---- weight setup: transpose to [c][o2] pair layout (2 pairs/thread) ----
#pragma unroll
    for (int s = 0; s < 2; s++) {
        int i = tid * 2 + s;                 // 0..255
        int c = i >> 3, o2 = i & 7;
        wqT[i] = make_float2(Wq[(2*o2)*CH_IN + c], Wq[(2*o2+1)*CH_IN + c]);
        wkT[i] = make_float2(Wk[(2*o2)*CH_IN + c], Wk[(2*o2+1)*CH_IN + c]);
        wvT[i] = make_float2(Wv[(2*o2)*CH_IN + c], Wv[(2*o2+1)*CH_IN + c]);
    }
    wy_s[tid] = ((const float4*)Wy)[tid];    // rows have o contiguous already
    if (tid < 8) {
        bq2[tid] = make_float2(bq[2*tid], bq[2*tid+1]);
        bk2[tid] = make_float2(bk[2*tid], bk[2*tid+1]);
        bv2[tid] = make_float2(bv[2*tid], bv[2*tid+1]);
    }
    if (tid < CH_IN) by_s[tid] = by[tid];

    const int h = blockIdx.x & (IMG_H - 1);
    const int b = blockIdx.x >> 8;

    const size_t base = (size_t)b * CH_IN * CHS + (size_t)h * IMG_W;
    const float4* cg = (const float4*)(cin + base);
    const float4* pg = (const float4*)(pin + base);
    float4* ocg = (float4*)(out + (size_t)b * 2 * CH_IN * CHS + (size_t)CH_IN * CHS
                                + (size_t)h * IMG_W);
    float4* sp4 = (float4*)sp;

    // ---------------- Phase 1: stage p + concat copy of c ----------------
#pragma unroll
    for (int half = 0; half < 2; half++) {
        float4 cb[8], pb[8];
#pragma unroll
        for (int i = 0; i < 8; i++) {
            int idx = tid + (half * 8 + i) * NT;            // = ch*64 + w4
            int ch = idx >> 6, w4 = idx & 63;
            cb[i] = cg[(size_t)ch * CHS4 + w4];
            pb[i] = pg[(size_t)ch * CHS4 + w4];
        }
#pragma unroll
        for (int i = 0; i < 8; i++) {
            int idx = tid + (half * 8 + i) * NT;
            int ch = idx >> 6, w4 = idx & 63;
            ocg[(size_t)ch * CHS4 + w4] = cb[i];            // concat(c) half
            sp4[idx] = pb[i];
        }
    }
    __syncthreads();

    // ---------------- Phase 2a: q,k projection (o-packed) ----------------
    const float2* cp2 = (const float2*)(cin + base);        // + ch*CHS2 + tid
    const float2* sp2 = (const float2*)sp;                  // + ch*128 + tid

    uint64_t q[2][8], k[2][8];
#pragma unroll
    for (int o2 = 0; o2 < 8; o2++) {
        F2U t; t.f = bq2[o2]; q[0][o2] = t.u; q[1][o2] = t.u;
        t.f = bk2[o2]; k[0][o2] = t.u; k[1][o2] = t.u;
    }

#pragma unroll
    for (int c4 = 0; c4 < CH_IN / 4; c4++) {
        float2 cv[4], pv[4];
#pragma unroll
        for (int j = 0; j < 4; j++) {
            int ch = c4 * 4 + j;
            cv[j] = cp2[(size_t)ch * CHS2 + tid];           // L2-resident re-read
            pv[j] = sp2[ch * (IMG_W / 2) + tid];
        }
#pragma unroll
        for (int j = 0; j < 4; j++) {
            const int ch = c4 * 4 + j;
            const ulonglong2* wq2 = (const ulonglong2*)&wqT[ch * 8];
            const ulonglong2* wk2 = (const ulonglong2*)&wkT[ch * 8];
            uint64_t cx0 = dup2(cv[j].x), cx1 = dup2(cv[j].y);
            uint64_t px0 = dup2(pv[j].x), px1 = dup2(pv[j].y);
#pragma unroll
            for (int m = 0; m < 4; m++) {                   // 2 o-pairs per m
                ulonglong2 a = wq2[m];
                fma2(q[0][2*m+0], a.x, cx0); fma2(q[0][2*m+1], a.y, cx0);
                fma2(q[1][2*m+0], a.x, cx1); fma2(q[1][2*m+1], a.y, cx1);
                ulonglong2 bm = wk2[m];
                fma2(k[0][2*m+0], bm.x, px0); fma2(k[0][2*m+1], bm.y, px0);
                fma2(k[1][2*m+0], bm.x, px1); fma2(k[1][2*m+1], bm.y, px1);
            }
        }
    }

    // exp(q*k), packed over o-pairs. No max-subtraction: |q*k| O(1..10),
    // fp32 exp safe; result identical after normalization.
    F2U e[2][8];
#pragma unroll
    for (int px = 0; px < 2; px++)
#pragma unroll
        for (int o2 = 0; o2 < 8; o2++) {
            F2U pr; pr.u = mul2(q[px][o2], k[px][o2]);
            e[px][o2].f.x = __expf(pr.f.x);
            e[px][o2].f.y = __expf(pr.f.y);
        }

    // ---------------- softmax reduction over width (packed) ----------------
    const int lane = tid & 31;
    const int wrp  = tid >> 5;
#pragma unroll
    for (int o2 = 0; o2 < 8; o2++) {
        uint64_t s = add2(e[0][o2].u, e[1][o2].u);
#pragma unroll
        for (int d = 16; d > 0; d >>= 1)
            s = add2(s, __shfl_xor_sync(0xffffffffu, (unsigned long long)s, d));
        if (lane == 0) red[wrp][o2] = s;
    }
    __syncthreads();

    uint64_t inv2[8];
#pragma unroll
    for (int o2 = 0; o2 < 8; o2++) {
        F2U t; t.u = add2(add2(red[0][o2], red[1][o2]), add2(red[2][o2], red[3][o2]));
        F2U r; r.f.x = __frcp_rn(t.f.x); r.f.y = __frcp_rn(t.f.y);
        inv2[o2] = r.u;
    }

    // ---------------- Phase 2b: v projection (o-packed) ----------------
    uint64_t v[2][8];
#pragma unroll
    for (int o2 = 0; o2 < 8; o2++) {
        F2U t; t.f = bv2[o2]; v[0][o2] = t.u; v[1][o2] = t.u;
    }

#pragma unroll
    for (int c4 = 0; c4 < CH_IN / 4; c4++) {
        float2 pv[4];
#pragma unroll
        for (int j = 0; j < 4; j++)
            pv[j] = sp2[(c4 * 4 + j) * (IMG_W / 2) + tid];
#pragma unroll
        for (int j = 0; j < 4; j++) {
            const int ch = c4 * 4 + j;
            const ulonglong2* wv2 = (const ulonglong2*)&wvT[ch * 8];
            uint64_t px0 = dup2(pv[j].x), px1 = dup2(pv[j].y);
#pragma unroll
            for (int m = 0; m < 4; m++) {
                ulonglong2 a = wv2[m];
                fma2(v[0][2*m+0], a.x, px0); fma2(v[0][2*m+1], a.y, px0);
                fma2(v[1][2*m+0], a.x, px1); fma2(v[1][2*m+1], a.y, px1);
            }
        }
    }

    // y = softmax(q*k) * v, packed (overwrite e)
#pragma unroll
    for (int px = 0; px < 2; px++)
#pragma unroll
        for (int o2 = 0; o2 < 8; o2++)
            e[px][o2].u = mul2(mul2(e[px][o2].u, inv2[o2]), v[px][o2]);

    // ---------------- output conv1x1 (packed o-pairs + horizontal add) -----
    float2* oy2 = (float2*)(out + (size_t)b * 2 * CH_IN * CHS + (size_t)h * IMG_W);
    const ulonglong2* wy2 = (const ulonglong2*)wy_s;        // 4 per ic
#pragma unroll
    for (int ic = 0; ic < CH_IN; ic++) {
        F2U a0; a0.f = make_float2(by_s[ic], 0.f);
        uint64_t acc0 = a0.u, acc1 = a0.u;
#pragma unroll
        for (int m = 0; m < 4; m++) {
            ulonglong2 w = wy2[ic * 4 + m];
            fma2(acc0, w.x, e[0][2*m+0].u); fma2(acc0, w.y, e[0][2*m+1].u);
            fma2(acc1, w.x, e[1][2*m+0].u); fma2(acc1, w.y, e[1][2*m+1].u);
        }
        F2U r0, r1; r0.u = acc0; r1.u = acc1;
        oy2[(size_t)ic * CHS2 + tid] = make_float2(r0.f.x + r0.f.y,
                                                   r1.f.x + r1.f.y);
    }
}

extern "C" void kernel_launch(void* const* d_in, const int* in_sizes, int n_in,
                              void* d_out, int out_size)
{
    cross_attn_kernel<<<NB * IMG_H, NT>>>(
        (const float*)d_in[0],  // c
        (const float*)d_in[1],  // p
        (const float*)d_in[2],  // Wq
        (const float*)d_in[3],  // bq
        (const float*)d_in[4],  // Wk
        (const float*)d_in[5],  // bk
        (const float*)d_in[6],  // Wv
        (const float*)d_in[7],  // bv
        (const float*)d_in[8],  // Wy
        (const float*)d_in[9],  // by
        (float*)d_out);
}